// round 16
// baseline (speedup 1.0000x reference)
#include <cuda_runtime.h>
#include <cuda_fp16.h>
#include <cuda_bf16.h>
#include <cstdint>

#define DIM 128
#define N_NODES_MAX 50000
#define N_EDGES_MAX 640000
#define BUCKET 64
#define TILE_M 64
#define NBUF 2
#define THREADS 384

// ---- device scratch (allocation-free rule: __device__ globals) ----
__device__ float g_side[(size_t)N_NODES_MAX * DIM];
__device__ int   g_cnt[N_NODES_MAX];
__device__ uint2 g_bucket[(size_t)N_NODES_MAX * BUCKET];
__device__ int   g_ovf_cnt;
__device__ uint4 g_ovf[N_EDGES_MAX];

// ---- dense smem layout (bytes). Rows 256B (128 fp16), XOR-swizzled. ----
#define ROWB 256
#define A_MAT8 (TILE_M * ROWB)          // 16384 per matrix
#define A_BUF  (4 * A_MAT8)             // 65536 per buffer (sh,sl,ph,pl)
#define SM_B1  0
#define SM_B2  512
#define SM_A   1024
#define SM_W   (SM_A + NBUF * A_BUF)    // 1024 + 131072 = 132096
#define W_MAT  (DIM * ROWB)             // 32768
#define SMEM_BYTES (SM_W + 2 * W_MAT)   // 197632

__device__ __forceinline__ uint32_t swz(int r, uint32_t colb) {
    return (uint32_t)r * ROWB + (colb ^ (((uint32_t)r & 7u) << 4));
}
__device__ __forceinline__ uint32_t pack_h2(float a, float b) {
    __half2 p = __halves2half2(__float2half_rn(a), __float2half_rn(b));
    return *reinterpret_cast<uint32_t*>(&p);
}
__device__ __forceinline__ void bar_syn(int id, int cnt) {
    asm volatile("bar.sync %0, %1;" :: "r"(id), "r"(cnt) : "memory");
}
__device__ __forceinline__ void bar_arr(int id, int cnt) {
    asm volatile("bar.arrive %0, %1;" :: "r"(id), "r"(cnt) : "memory");
}

// ---------------------------------------------------------------------------
// Bucket fill / SpMM / overflow fixup (unchanged control)
// ---------------------------------------------------------------------------
__global__ void bucket_fill(const int* __restrict__ rows,
                            const int* __restrict__ cols,
                            const float* __restrict__ vals, int E) {
    int e = blockIdx.x * blockDim.x + threadIdx.x;
    if (e >= E) return;
    int r = __ldg(&rows[e]);
    int c = __ldg(&cols[e]);
    float v = __ldg(&vals[e]);
    int p = atomicAdd(&g_cnt[r], 1);
    if (p < BUCKET) {
        g_bucket[(size_t)r * BUCKET + p] = make_uint2((uint32_t)c, __float_as_uint(v));
    } else {
        int q = atomicAdd(&g_ovf_cnt, 1);
        g_ovf[q] = make_uint4((uint32_t)r, (uint32_t)c, __float_as_uint(v), 0u);
    }
}

__global__ void spmm_bucket(const float* __restrict__ ego, int n) {
    int w = (blockIdx.x * blockDim.x + threadIdx.x) >> 5;
    if (w >= n) return;
    int lane = threadIdx.x & 31;

    int deg = g_cnt[w];
    if (deg > BUCKET) deg = BUCKET;
    const float4* ego4 = reinterpret_cast<const float4*>(ego);

    float4 acc = make_float4(0.f, 0.f, 0.f, 0.f);
    for (int base = 0; base < deg; base += 32) {
        uint2 slot = make_uint2(0u, 0u);
        if (base + lane < deg)
            slot = __ldg(&g_bucket[(size_t)w * BUCKET + base + lane]);
        int m = deg - base; if (m > 32) m = 32;
        #pragma unroll 4
        for (int j = 0; j < m; j++) {
            uint32_t cc = __shfl_sync(0xffffffffu, slot.x, j);
            float    vv = __uint_as_float(__shfl_sync(0xffffffffu, slot.y, j));
            float4 x = ego4[(size_t)cc * 32 + lane];
            acc.x += vv * x.x; acc.y += vv * x.y;
            acc.z += vv * x.z; acc.w += vv * x.w;
        }
    }
    reinterpret_cast<float4*>(g_side)[(size_t)w * 32 + lane] = acc;
}

__global__ void ovf_fixup(const float* __restrict__ ego) {
    int total = g_ovf_cnt;
    int gw = (blockIdx.x * blockDim.x + threadIdx.x) >> 5;
    int nw = (gridDim.x * blockDim.x) >> 5;
    int lane = threadIdx.x & 31;
    const float4* ego4 = reinterpret_cast<const float4*>(ego);
    for (int i = gw; i < total; i += nw) {
        uint4 t = g_ovf[i];
        float v = __uint_as_float(t.z);
        float4 x = ego4[(size_t)t.y * 32 + lane];
        float* dst = g_side + (size_t)t.x * DIM + lane * 4;
        asm volatile("red.global.add.v4.f32 [%0], {%1,%2,%3,%4};"
                     :: "l"(dst), "f"(v * x.x), "f"(v * x.y), "f"(v * x.z), "f"(v * x.w)
                     : "memory");
    }
}

// ---------------------------------------------------------------------------
// mma.sync / ldmatrix helpers (fp16)
// ---------------------------------------------------------------------------
__device__ __forceinline__ void ldsm_x4(uint32_t* r, uint32_t addr) {
    asm volatile("ldmatrix.sync.aligned.m8n8.x4.shared.b16 {%0,%1,%2,%3}, [%4];"
                 : "=r"(r[0]), "=r"(r[1]), "=r"(r[2]), "=r"(r[3]) : "r"(addr));
}
__device__ __forceinline__ void mma_f16(float* d, const uint32_t* a,
                                        uint32_t b0, uint32_t b1) {
    asm volatile("mma.sync.aligned.m16n8k16.row.col.f32.f16.f16.f32 "
                 "{%0,%1,%2,%3}, {%4,%5,%6,%7}, {%8,%9}, {%0,%1,%2,%3};"
                 : "+f"(d[0]), "+f"(d[1]), "+f"(d[2]), "+f"(d[3])
                 : "r"(a[0]), "r"(a[1]), "r"(a[2]), "r"(a[3]), "r"(b0), "r"(b1));
}
__device__ __forceinline__ float lrelu(float v) { return v > 0.f ? v : 0.01f * v; }

// ---------------------------------------------------------------------------
// Dense kernel: warp-specialized, fp16 2-term split, fp16 weights.
// 8 consumer warps (2m x 4n, warp tile 32x32, TILE_M=64), 4 producers.
// mb=2 halves weight-LDSM per row; TILE_M=64 halves barriers per row.
// ---------------------------------------------------------------------------
__global__ void __launch_bounds__(THREADS, 1)
dense_kernel(const float* __restrict__ ego,
             const float* __restrict__ W1, const float* __restrict__ b1,
             const float* __restrict__ W2, const float* __restrict__ b2,
             float* __restrict__ out, int n) {
    extern __shared__ char smc[];
    uint32_t sbase = (uint32_t)__cvta_generic_to_shared(smc);

    int tid  = threadIdx.x;
    int warp = tid >> 5;
    int lane = tid & 31;

    // ---- one-time: weights -> fp16 swizzled smem (all 384 threads) ----
    for (int i = tid; i < DIM * DIM; i += THREADS) {
        int o = i >> 7, k = i & 127;
        uint32_t off = swz(o, (uint32_t)k * 2);
        *reinterpret_cast<__half*>(smc + SM_W + 0 * W_MAT + off) =
            __float2half_rn(__ldg(&W1[i]));
        *reinterpret_cast<__half*>(smc + SM_W + 1 * W_MAT + off) =
            __float2half_rn(__ldg(&W2[i]));
    }
    for (int i = tid; i < DIM; i += THREADS) {
        reinterpret_cast<float*>(smc + SM_B1)[i] = __ldg(&b1[i]);
        reinterpret_cast<float*>(smc + SM_B2)[i] = __ldg(&b2[i]);
    }
    __syncthreads();

    int nt = (n + TILE_M - 1) / TILE_M;
    const float4* ego4  = reinterpret_cast<const float4*>(ego);
    const float4* side4 = reinterpret_cast<const float4*>(g_side);

    if (warp >= 8) {
        // ============ PRODUCER (warps 8-11, 128 threads) ============
        int pt = tid - 256;
        int k = 0;
        for (int t = blockIdx.x; t < nt; t += gridDim.x, k++) {
            int b = k % NBUF;
            if (k >= NBUF) bar_syn(6 + b, THREADS);   // wait buffer free
            char* abuf = smc + SM_A + b * A_BUF;
            int row0 = t * TILE_M;

            for (int i = pt; i < TILE_M * 32; i += 128) {
                int r  = i >> 5;
                int c4 = i & 31;
                int row = row0 + r;
                float4 e = make_float4(0.f, 0.f, 0.f, 0.f);
                float4 d = e;
                if (row < n) {
                    e = ego4[(size_t)row * 32 + c4];
                    d = side4[(size_t)row * 32 + c4];
                }
                // bf16 round of side (matches reference)
                d.x = __bfloat162float(__float2bfloat16(d.x));
                d.y = __bfloat162float(__float2bfloat16(d.y));
                d.z = __bfloat162float(__float2bfloat16(d.z));
                d.w = __bfloat162float(__float2bfloat16(d.w));
                float4 s = make_float4(e.x + d.x, e.y + d.y, e.z + d.z, e.w + d.w);
                float4 p = make_float4(e.x * d.x, e.y * d.y, e.z * d.z, e.w * d.w);

                uint32_t off = swz(r, (uint32_t)c4 * 8);
                // fp16 hi/lo split (hi = rn(x), lo = rn(x - hi))
                float shx = __half2float(__float2half_rn(s.x));
                float shy = __half2float(__float2half_rn(s.y));
                float shz = __half2float(__float2half_rn(s.z));
                float shw = __half2float(__float2half_rn(s.w));
                uint2 u;
                u.x = pack_h2(s.x, s.y); u.y = pack_h2(s.z, s.w);
                *reinterpret_cast<uint2*>(abuf + 0 * A_MAT8 + off) = u;
                u.x = pack_h2(s.x - shx, s.y - shy); u.y = pack_h2(s.z - shz, s.w - shw);
                *reinterpret_cast<uint2*>(abuf + 1 * A_MAT8 + off) = u;

                float phx = __half2float(__float2half_rn(p.x));
                float phy = __half2float(__float2half_rn(p.y));
                float phz = __half2float(__float2half_rn(p.z));
                float phw = __half2float(__float2half_rn(p.w));
                u.x = pack_h2(p.x, p.y); u.y = pack_h2(p.z, p.w);
                *reinterpret_cast<uint2*>(abuf + 2 * A_MAT8 + off) = u;
                u.x = pack_h2(p.x - phx, p.y - phy); u.y = pack_h2(p.z - phz, p.w - phw);
                *reinterpret_cast<uint2*>(abuf + 3 * A_MAT8 + off) = u;
            }
            __threadfence_block();            // STS visible before full-arrive
            bar_arr(1 + b, THREADS);          // signal buffer full
        }
    } else {
        // ============ CONSUMER (warps 0-7, 256 threads) ============
        int warp_m = (warp >> 2) * 32;        // 0,32  (mb adds 0/16)
        int warp_n = (warp & 3) * 32;         // 0,32,64,96
        int lrow   = lane & 15;
        int lchunk = (lane >> 4) * 16;

        int col_base = warp_n + (lane & 3) * 2;
        float2 b1v[4], b2v[4];
        #pragma unroll
        for (int nb = 0; nb < 4; nb++) {
            b1v[nb] = *reinterpret_cast<const float2*>(
                          reinterpret_cast<const float*>(smc + SM_B1) + col_base + nb * 8);
            b2v[nb] = *reinterpret_cast<const float2*>(
                          reinterpret_cast<const float*>(smc + SM_B2) + col_base + nb * 8);
        }

        uint32_t arow[2];
        #pragma unroll
        for (int mb = 0; mb < 2; mb++)
            arow[mb] = (uint32_t)(warp_m + mb * 16 + lrow) * ROWB;
        uint32_t xr_a = (uint32_t)((warp_m + lrow) & 7) << 4;   // mb*16 preserves r&7
        uint32_t b_addr[2];
        #pragma unroll
        for (int np = 0; np < 2; np++)
            b_addr[np] = sbase + SM_W + (uint32_t)(warp_n + np * 16 + lrow) * ROWB;
        uint32_t xr_b = (uint32_t)((warp_n + lrow) & 7) << 4;

        int k = 0;
        for (int t = blockIdx.x; t < nt; t += gridDim.x, k++) {
            int b = k % NBUF;
            bar_syn(1 + b, THREADS);          // wait buffer full
            uint32_t abase = sbase + SM_A + b * A_BUF;
            int row0 = t * TILE_M;

            float d1[2][4][4], d2[2][4][4];
            #pragma unroll
            for (int mb = 0; mb < 2; mb++)
                #pragma unroll
                for (int nb = 0; nb < 4; nb++)
                    #pragma unroll
                    for (int j = 0; j < 4; j++) { d1[mb][nb][j] = 0.f; d2[mb][nb][j] = 0.f; }

            #pragma unroll
            for (int ks = 0; ks < 8; ks++) {
                uint32_t kA = ((uint32_t)(ks * 32 + lchunk)) ^ xr_a;
                uint32_t kB = ((uint32_t)(ks * 32 + lchunk)) ^ xr_b;

                uint32_t sh[2][4], sl[2][4], ph[2][4], pl[2][4];
                #pragma unroll
                for (int mb = 0; mb < 2; mb++) {
                    ldsm_x4(sh[mb], abase + arow[mb] + 0 * A_MAT8 + kA);
                    ldsm_x4(sl[mb], abase + arow[mb] + 1 * A_MAT8 + kA);
                    ldsm_x4(ph[mb], abase + arow[mb] + 2 * A_MAT8 + kA);
                    ldsm_x4(pl[mb], abase + arow[mb] + 3 * A_MAT8 + kA);
                }

                uint32_t w1f[2][4], w2f[2][4];
                #pragma unroll
                for (int np = 0; np < 2; np++) {
                    ldsm_x4(w1f[np], b_addr[np] + 0 * W_MAT + kB);
                    ldsm_x4(w2f[np], b_addr[np] + 1 * W_MAT + kB);
                }

                #pragma unroll
                for (int mb = 0; mb < 2; mb++) {
                    #pragma unroll
                    for (int np = 0; np < 2; np++) {
                        #pragma unroll
                        for (int j = 0; j < 2; j++) {
                            int nb = np * 2 + j;
                            mma_f16(d1[mb][nb], sh[mb], w1f[np][j], w1f[np][j + 2]);
                            mma_f16(d1[mb][nb], sl[mb], w1f[np][j], w1f[np][j + 2]);
                            mma_f16(d2[mb][nb], ph[mb], w2f[np][j], w2f[np][j + 2]);
                            mma_f16(d2[mb][nb], pl[mb], w2f[np][j], w2f[np][j + 2]);
                        }
                    }
                }
            }
            bar_arr(6 + b, THREADS);          // buffer consumed -> free

            // epilogue (overlaps producer's next fill)
            #pragma unroll
            for (int mb = 0; mb < 2; mb++) {
                int r_lo = row0 + warp_m + mb * 16 + (lane >> 2);
                int r_hi = r_lo + 8;
                #pragma unroll
                for (int nb = 0; nb < 4; nb++) {
                    int col = col_base + nb * 8;
                    if (r_lo < n) {
                        float2 o;
                        o.x = lrelu(d1[mb][nb][0] + b1v[nb].x) + lrelu(d2[mb][nb][0] + b2v[nb].x);
                        o.y = lrelu(d1[mb][nb][1] + b1v[nb].y) + lrelu(d2[mb][nb][1] + b2v[nb].y);
                        *reinterpret_cast<float2*>(out + (size_t)r_lo * DIM + col) = o;
                    }
                    if (r_hi < n) {
                        float2 o;
                        o.x = lrelu(d1[mb][nb][2] + b1v[nb].x) + lrelu(d2[mb][nb][2] + b2v[nb].x);
                        o.y = lrelu(d1[mb][nb][3] + b1v[nb].y) + lrelu(d2[mb][nb][3] + b2v[nb].y);
                        *reinterpret_cast<float2*>(out + (size_t)r_hi * DIM + col) = o;
                    }
                }
            }
        }
    }
}

// ---------------------------------------------------------------------------
extern "C" void kernel_launch(void* const* d_in, const int* in_sizes, int n_in,
                              void* d_out, int out_size) {
    const float* ego  = (const float*)d_in[0];
    const float* vals = (const float*)d_in[1];
    const float* W1   = (const float*)d_in[2];
    const float* b1   = (const float*)d_in[3];
    const float* W2   = (const float*)d_in[4];
    const float* b2   = (const float*)d_in[5];
    const int*   rows = (const int*)d_in[6];
    const int*   cols = (const int*)d_in[7];
    float*       out  = (float*)d_out;

    int n = in_sizes[0] / DIM;   // 50000
    int E = in_sizes[1];         // 640000

    cudaFuncSetAttribute(dense_kernel,
                         cudaFuncAttributeMaxDynamicSharedMemorySize, SMEM_BYTES);

    // 1) reset bucket cursors + overflow counter
    void* cnt_ptr = nullptr;
    cudaGetSymbolAddress(&cnt_ptr, g_cnt);
    cudaMemsetAsync(cnt_ptr, 0, (size_t)n * sizeof(int));
    void* ovf_ptr = nullptr;
    cudaGetSymbolAddress(&ovf_ptr, g_ovf_cnt);
    cudaMemsetAsync(ovf_ptr, 0, sizeof(int));

    // 2) bucket fill
    bucket_fill<<<(E + 255) / 256, 256>>>(rows, cols, vals, E);

    // 3) bucket SpMM (whole-chip edge parallelism — do NOT fuse into dense)
    spmm_bucket<<<(n * 32 + 255) / 256, 256>>>(ego, n);

    // 4) overflow fixup
    ovf_fixup<<<64, 256>>>(ego);

    // 5) fused dense (8 consumers mb=2 / 4 producers, TILE_M=64)
    dense_kernel<<<148, THREADS, SMEM_BYTES>>>(ego, W1, b1, W2, b2, out, n);
}

// round 17
// speedup vs baseline: 1.1601x; 1.1601x over previous
#include <cuda_runtime.h>
#include <cuda_fp16.h>
#include <cuda_bf16.h>
#include <cstdint>

#define DIM 128
#define N_NODES_MAX 50000
#define N_EDGES_MAX 640000
#define BUCKET 64
#define TILE_M 32
#define NBUF 5
#define THREADS 384

// ---- device scratch (allocation-free rule: __device__ globals) ----
__device__ float g_side[(size_t)N_NODES_MAX * DIM];
__device__ int   g_cnt[N_NODES_MAX];
__device__ uint2 g_bucket[(size_t)N_NODES_MAX * BUCKET];
__device__ int   g_ovf_cnt;
__device__ uint4 g_ovf[N_EDGES_MAX];

// ---- dense smem layout (bytes). Rows 256B (128 fp16), XOR-swizzled. ----
#define ROWB 256
#define A_MAT8 (TILE_M * ROWB)          // 8192 per matrix
#define A_BUF  (2 * A_MAT8)             // 16384 per buffer (s, p)
#define SM_B1  0
#define SM_B2  512
#define SM_A   1024
#define SM_W   (SM_A + NBUF * A_BUF)    // 1024 + 81920 = 82944
#define W_MAT  (DIM * ROWB)             // 32768
#define SMEM_BYTES (SM_W + 2 * W_MAT)   // 148480

__device__ __forceinline__ uint32_t swz(int r, uint32_t colb) {
    return (uint32_t)r * ROWB + (colb ^ (((uint32_t)r & 7u) << 4));
}
__device__ __forceinline__ uint32_t pack_h2(float a, float b) {
    __half2 p = __halves2half2(__float2half_rn(a), __float2half_rn(b));
    return *reinterpret_cast<uint32_t*>(&p);
}
__device__ __forceinline__ void bar_syn(int id, int cnt) {
    asm volatile("bar.sync %0, %1;" :: "r"(id), "r"(cnt) : "memory");
}
__device__ __forceinline__ void bar_arr(int id, int cnt) {
    asm volatile("bar.arrive %0, %1;" :: "r"(id), "r"(cnt) : "memory");
}

// ---------------------------------------------------------------------------
// Bucket fill / SpMM / overflow fixup (unchanged control)
// ---------------------------------------------------------------------------
__global__ void bucket_fill(const int* __restrict__ rows,
                            const int* __restrict__ cols,
                            const float* __restrict__ vals, int E) {
    int e = blockIdx.x * blockDim.x + threadIdx.x;
    if (e >= E) return;
    int r = __ldg(&rows[e]);
    int c = __ldg(&cols[e]);
    float v = __ldg(&vals[e]);
    int p = atomicAdd(&g_cnt[r], 1);
    if (p < BUCKET) {
        g_bucket[(size_t)r * BUCKET + p] = make_uint2((uint32_t)c, __float_as_uint(v));
    } else {
        int q = atomicAdd(&g_ovf_cnt, 1);
        g_ovf[q] = make_uint4((uint32_t)r, (uint32_t)c, __float_as_uint(v), 0u);
    }
}

__global__ void spmm_bucket(const float* __restrict__ ego, int n) {
    int w = (blockIdx.x * blockDim.x + threadIdx.x) >> 5;
    if (w >= n) return;
    int lane = threadIdx.x & 31;

    int deg = g_cnt[w];
    if (deg > BUCKET) deg = BUCKET;
    const float4* ego4 = reinterpret_cast<const float4*>(ego);

    float4 acc = make_float4(0.f, 0.f, 0.f, 0.f);
    for (int base = 0; base < deg; base += 32) {
        uint2 slot = make_uint2(0u, 0u);
        if (base + lane < deg)
            slot = __ldg(&g_bucket[(size_t)w * BUCKET + base + lane]);
        int m = deg - base; if (m > 32) m = 32;
        #pragma unroll 4
        for (int j = 0; j < m; j++) {
            uint32_t cc = __shfl_sync(0xffffffffu, slot.x, j);
            float    vv = __uint_as_float(__shfl_sync(0xffffffffu, slot.y, j));
            float4 x = ego4[(size_t)cc * 32 + lane];
            acc.x += vv * x.x; acc.y += vv * x.y;
            acc.z += vv * x.z; acc.w += vv * x.w;
        }
    }
    reinterpret_cast<float4*>(g_side)[(size_t)w * 32 + lane] = acc;
}

__global__ void ovf_fixup(const float* __restrict__ ego) {
    int total = g_ovf_cnt;
    int gw = (blockIdx.x * blockDim.x + threadIdx.x) >> 5;
    int nw = (gridDim.x * blockDim.x) >> 5;
    int lane = threadIdx.x & 31;
    const float4* ego4 = reinterpret_cast<const float4*>(ego);
    for (int i = gw; i < total; i += nw) {
        uint4 t = g_ovf[i];
        float v = __uint_as_float(t.z);
        float4 x = ego4[(size_t)t.y * 32 + lane];
        float* dst = g_side + (size_t)t.x * DIM + lane * 4;
        asm volatile("red.global.add.v4.f32 [%0], {%1,%2,%3,%4};"
                     :: "l"(dst), "f"(v * x.x), "f"(v * x.y), "f"(v * x.z), "f"(v * x.w)
                     : "memory");
    }
}

// ---------------------------------------------------------------------------
// mma.sync / ldmatrix helpers (fp16)
// ---------------------------------------------------------------------------
__device__ __forceinline__ void ldsm_x4(uint32_t* r, uint32_t addr) {
    asm volatile("ldmatrix.sync.aligned.m8n8.x4.shared.b16 {%0,%1,%2,%3}, [%4];"
                 : "=r"(r[0]), "=r"(r[1]), "=r"(r[2]), "=r"(r[3]) : "r"(addr));
}
__device__ __forceinline__ void mma_f16(float* d, const uint32_t* a,
                                        uint32_t b0, uint32_t b1) {
    asm volatile("mma.sync.aligned.m16n8k16.row.col.f32.f16.f16.f32 "
                 "{%0,%1,%2,%3}, {%4,%5,%6,%7}, {%8,%9}, {%0,%1,%2,%3};"
                 : "+f"(d[0]), "+f"(d[1]), "+f"(d[2]), "+f"(d[3])
                 : "r"(a[0]), "r"(a[1]), "r"(a[2]), "r"(a[3]), "r"(b0), "r"(b1));
}
__device__ __forceinline__ float lrelu(float v) { return v > 0.f ? v : 0.01f * v; }

// ---------------------------------------------------------------------------
// Dense kernel: warp-specialized, single-term fp16 (inputs AND weights fp16).
// Error budget: input rnd 2^-12 + weight rnd 2^-12 -> ~2.7e-4 << 1e-3.
// 8 consumer warps (2m x 4n, warp tile 16x32, TILE_M=32), 4 producers.
// ---------------------------------------------------------------------------
__global__ void __launch_bounds__(THREADS, 1)
dense_kernel(const float* __restrict__ ego,
             const float* __restrict__ W1, const float* __restrict__ b1,
             const float* __restrict__ W2, const float* __restrict__ b2,
             float* __restrict__ out, int n) {
    extern __shared__ char smc[];
    uint32_t sbase = (uint32_t)__cvta_generic_to_shared(smc);

    int tid  = threadIdx.x;
    int warp = tid >> 5;
    int lane = tid & 31;

    // ---- one-time: weights -> fp16 swizzled smem (all 384 threads) ----
    for (int i = tid; i < DIM * DIM; i += THREADS) {
        int o = i >> 7, k = i & 127;
        uint32_t off = swz(o, (uint32_t)k * 2);
        *reinterpret_cast<__half*>(smc + SM_W + 0 * W_MAT + off) =
            __float2half_rn(__ldg(&W1[i]));
        *reinterpret_cast<__half*>(smc + SM_W + 1 * W_MAT + off) =
            __float2half_rn(__ldg(&W2[i]));
    }
    for (int i = tid; i < DIM; i += THREADS) {
        reinterpret_cast<float*>(smc + SM_B1)[i] = __ldg(&b1[i]);
        reinterpret_cast<float*>(smc + SM_B2)[i] = __ldg(&b2[i]);
    }
    __syncthreads();

    int nt = (n + TILE_M - 1) / TILE_M;
    const float4* ego4  = reinterpret_cast<const float4*>(ego);
    const float4* side4 = reinterpret_cast<const float4*>(g_side);

    if (warp >= 8) {
        // ============ PRODUCER (warps 8-11, 128 threads) ============
        int pt = tid - 256;
        int k = 0;
        for (int t = blockIdx.x; t < nt; t += gridDim.x, k++) {
            int b = k % NBUF;
            if (k >= NBUF) bar_syn(6 + b, THREADS);   // wait buffer free
            char* abuf = smc + SM_A + b * A_BUF;
            int row0 = t * TILE_M;

            for (int i = pt; i < TILE_M * 32; i += 128) {
                int r  = i >> 5;
                int c4 = i & 31;
                int row = row0 + r;
                float4 e = make_float4(0.f, 0.f, 0.f, 0.f);
                float4 d = e;
                if (row < n) {
                    e = ego4[(size_t)row * 32 + c4];
                    d = side4[(size_t)row * 32 + c4];
                }
                // bf16 round of side (matches reference)
                d.x = __bfloat162float(__float2bfloat16(d.x));
                d.y = __bfloat162float(__float2bfloat16(d.y));
                d.z = __bfloat162float(__float2bfloat16(d.z));
                d.w = __bfloat162float(__float2bfloat16(d.w));
                float4 s = make_float4(e.x + d.x, e.y + d.y, e.z + d.z, e.w + d.w);
                float4 p = make_float4(e.x * d.x, e.y * d.y, e.z * d.z, e.w * d.w);

                uint32_t off = swz(r, (uint32_t)c4 * 8);
                uint2 u;
                u.x = pack_h2(s.x, s.y); u.y = pack_h2(s.z, s.w);
                *reinterpret_cast<uint2*>(abuf + 0 * A_MAT8 + off) = u;
                u.x = pack_h2(p.x, p.y); u.y = pack_h2(p.z, p.w);
                *reinterpret_cast<uint2*>(abuf + 1 * A_MAT8 + off) = u;
            }
            __threadfence_block();            // STS visible before full-arrive
            bar_arr(1 + b, THREADS);          // signal buffer full
        }
    } else {
        // ============ CONSUMER (warps 0-7, 256 threads) ============
        int warp_m = (warp >> 2) * 16;        // 0,16
        int warp_n = (warp & 3) * 32;         // 0,32,64,96
        int lrow   = lane & 15;
        int lchunk = (lane >> 4) * 16;

        int col_base = warp_n + (lane & 3) * 2;
        float2 b1v[4], b2v[4];
        #pragma unroll
        for (int nb = 0; nb < 4; nb++) {
            b1v[nb] = *reinterpret_cast<const float2*>(
                          reinterpret_cast<const float*>(smc + SM_B1) + col_base + nb * 8);
            b2v[nb] = *reinterpret_cast<const float2*>(
                          reinterpret_cast<const float*>(smc + SM_B2) + col_base + nb * 8);
        }

        uint32_t arow = (uint32_t)(warp_m + lrow) * ROWB;
        uint32_t xr_a = (uint32_t)((warp_m + lrow) & 7) << 4;
        uint32_t b_addr[2];
        #pragma unroll
        for (int np = 0; np < 2; np++)
            b_addr[np] = sbase + SM_W + (uint32_t)(warp_n + np * 16 + lrow) * ROWB;
        uint32_t xr_b = (uint32_t)((warp_n + lrow) & 7) << 4;

        int k = 0;
        for (int t = blockIdx.x; t < nt; t += gridDim.x, k++) {
            int b = k % NBUF;
            bar_syn(1 + b, THREADS);          // wait buffer full
            uint32_t abase = sbase + SM_A + b * A_BUF + arow;
            int row0 = t * TILE_M;

            float d1[4][4], d2[4][4];
            #pragma unroll
            for (int nb = 0; nb < 4; nb++)
                #pragma unroll
                for (int j = 0; j < 4; j++) { d1[nb][j] = 0.f; d2[nb][j] = 0.f; }

            #pragma unroll
            for (int ks = 0; ks < 8; ks++) {
                uint32_t kA = ((uint32_t)(ks * 32 + lchunk)) ^ xr_a;
                uint32_t kB = ((uint32_t)(ks * 32 + lchunk)) ^ xr_b;

                uint32_t sfr[4], pfr[4];
                ldsm_x4(sfr, abase + 0 * A_MAT8 + kA);
                ldsm_x4(pfr, abase + 1 * A_MAT8 + kA);

                uint32_t w1f[2][4], w2f[2][4];
                #pragma unroll
                for (int np = 0; np < 2; np++) {
                    ldsm_x4(w1f[np], b_addr[np] + 0 * W_MAT + kB);
                    ldsm_x4(w2f[np], b_addr[np] + 1 * W_MAT + kB);
                }

                #pragma unroll
                for (int np = 0; np < 2; np++) {
                    #pragma unroll
                    for (int j = 0; j < 2; j++) {
                        int nb = np * 2 + j;
                        mma_f16(d1[nb], sfr, w1f[np][j], w1f[np][j + 2]);
                        mma_f16(d2[nb], pfr, w2f[np][j], w2f[np][j + 2]);
                    }
                }
            }
            bar_arr(6 + b, THREADS);          // buffer consumed -> free

            // epilogue (overlaps producer's next fill)
            int r_lo = row0 + warp_m + (lane >> 2);
            int r_hi = r_lo + 8;
            #pragma unroll
            for (int nb = 0; nb < 4; nb++) {
                int col = col_base + nb * 8;
                if (r_lo < n) {
                    float2 o;
                    o.x = lrelu(d1[nb][0] + b1v[nb].x) + lrelu(d2[nb][0] + b2v[nb].x);
                    o.y = lrelu(d1[nb][1] + b1v[nb].y) + lrelu(d2[nb][1] + b2v[nb].y);
                    *reinterpret_cast<float2*>(out + (size_t)r_lo * DIM + col) = o;
                }
                if (r_hi < n) {
                    float2 o;
                    o.x = lrelu(d1[nb][2] + b1v[nb].x) + lrelu(d2[nb][2] + b2v[nb].x);
                    o.y = lrelu(d1[nb][3] + b1v[nb].y) + lrelu(d2[nb][3] + b2v[nb].y);
                    *reinterpret_cast<float2*>(out + (size_t)r_hi * DIM + col) = o;
                }
            }
        }
    }
}

// ---------------------------------------------------------------------------
extern "C" void kernel_launch(void* const* d_in, const int* in_sizes, int n_in,
                              void* d_out, int out_size) {
    const float* ego  = (const float*)d_in[0];
    const float* vals = (const float*)d_in[1];
    const float* W1   = (const float*)d_in[2];
    const float* b1   = (const float*)d_in[3];
    const float* W2   = (const float*)d_in[4];
    const float* b2   = (const float*)d_in[5];
    const int*   rows = (const int*)d_in[6];
    const int*   cols = (const int*)d_in[7];
    float*       out  = (float*)d_out;

    int n = in_sizes[0] / DIM;   // 50000
    int E = in_sizes[1];         // 640000

    cudaFuncSetAttribute(dense_kernel,
                         cudaFuncAttributeMaxDynamicSharedMemorySize, SMEM_BYTES);

    // 1) reset bucket cursors + overflow counter
    void* cnt_ptr = nullptr;
    cudaGetSymbolAddress(&cnt_ptr, g_cnt);
    cudaMemsetAsync(cnt_ptr, 0, (size_t)n * sizeof(int));
    void* ovf_ptr = nullptr;
    cudaGetSymbolAddress(&ovf_ptr, g_ovf_cnt);
    cudaMemsetAsync(ovf_ptr, 0, sizeof(int));

    // 2) bucket fill
    bucket_fill<<<(E + 255) / 256, 256>>>(rows, cols, vals, E);

    // 3) bucket SpMM (whole-chip edge parallelism — do NOT fuse into dense)
    spmm_bucket<<<(n * 32 + 255) / 256, 256>>>(ego, n);

    // 4) overflow fixup
    ovf_fixup<<<64, 256>>>(ego);

    // 5) fused dense (warp-specialized, single-term fp16)
    dense_kernel<<<148, THREADS, SMEM_BYTES>>>(ego, W1, b1, W2, b2, out, n);
}